// round 1
// baseline (speedup 1.0000x reference)
#include <cuda_runtime.h>

// Problem constants (fixed by the reference)
#define DB 2     // batch
#define DL 64    // L
#define DT 32    // T
#define DD 256   // D
#define G  8     // j-columns per block in the main kernel

// Scratch (device globals: no allocation allowed)
__device__ float g_Qk[DB * DL * DD];      // (Q@Wk) per (b,i), pre-scaled; 128x256
__device__ float g_WcombT[DD * DD];       // WcombT[d*256+f] = sum_e Wf[f,e]*Wv[e,d]
__device__ float g_bcomb[DD];             // bcomb[f] = sum_e Wf[f,e]*bv[e] + bf[f]

// ---------------------------------------------------------------------------
// Prologue 1: Qk[b,i,d] = sum_e Q[b,i,e] * Wk[e,d],
//             Q = (query@Wq^T + bq) / sqrt(D)
// grid = 128 (one per (b,i)), block = 256
// ---------------------------------------------------------------------------
__global__ void qk_kernel(const float* __restrict__ query,
                          const float* __restrict__ Wq,
                          const float* __restrict__ bq,
                          const float* __restrict__ Wk) {
    const int bi = blockIdx.x;
    const int e  = threadIdx.x;
    __shared__ float qrow[DD];
    __shared__ float Qs[DD];

    qrow[e] = query[bi * DD + e];
    __syncthreads();

    // Q[e] = (query[bi,:] . Wq[e,:] + bq[e]) / 16
    float acc = bq[e];
    const float* wq = Wq + (size_t)e * DD;
#pragma unroll 8
    for (int d = 0; d < DD; d++) acc += qrow[d] * wq[d];
    Qs[e] = acc * 0.0625f;   // 1/sqrt(256)
    __syncthreads();

    // Qk[d] = sum_e Qs[e] * Wk[e,d]   (coalesced over d = threadIdx.x)
    const int d = e;
    float s = 0.f;
#pragma unroll 8
    for (int ee = 0; ee < DD; ee++) s += Qs[ee] * Wk[(size_t)ee * DD + d];
    g_Qk[bi * DD + d] = s;
}

// ---------------------------------------------------------------------------
// Prologue 2: WcombT[d,f] = sum_e Wv[e,d] * Wf[f,e]   (tiled 32x32 GEMM)
// grid = (8,8), block = (32,32)
// ---------------------------------------------------------------------------
__global__ void wcomb_kernel(const float* __restrict__ Wv,
                             const float* __restrict__ Wf) {
    __shared__ float Av[32][33];   // Av[k][m] = Wv[e0+k, d0+m]
    __shared__ float Bf[32][33];   // Bf[m][k] = Wf[f0+m, e0+k]
    const int tx = threadIdx.x, ty = threadIdx.y;
    const int f0 = blockIdx.x * 32, d0 = blockIdx.y * 32;

    float acc = 0.f;
    for (int e0 = 0; e0 < DD; e0 += 32) {
        Av[ty][tx] = Wv[(size_t)(e0 + ty) * DD + d0 + tx];
        Bf[ty][tx] = Wf[(size_t)(f0 + ty) * DD + e0 + tx];
        __syncthreads();
#pragma unroll
        for (int k = 0; k < 32; k++) acc += Av[k][ty] * Bf[tx][k];
        __syncthreads();
    }
    g_WcombT[(size_t)(d0 + ty) * DD + f0 + tx] = acc;
}

// ---------------------------------------------------------------------------
// Prologue 3: bcomb[f] = sum_e Wf[f,e]*bv[e] + bf[f]
// grid = 1, block = 256
// ---------------------------------------------------------------------------
__global__ void bcomb_kernel(const float* __restrict__ Wf,
                             const float* __restrict__ bv,
                             const float* __restrict__ bf) {
    const int f = threadIdx.x;
    __shared__ float bvs[DD];
    bvs[f] = bv[f];
    __syncthreads();
    float acc = bf[f];
    const float* wf = Wf + (size_t)f * DD;
#pragma unroll 8
    for (int e = 0; e < DD; e++) acc += wf[e] * bvs[e];
    g_bcomb[f] = acc;
}

// ---------------------------------------------------------------------------
// Main kernel: one streaming pass over key and value.
//   per (b,i,j):  scores[t] = key[b,i,j,t,:] . Qk[b,i,:]
//                 attn = softmax_t(scores)
//                 vbar[d] = sum_t attn[t] * value[b,i,j,t,d]
//                 out[b,i,j,f] = sum_d vbar[d]*WcombT[d,f] + bcomb[f]
// grid = B*L*L/G = 1024, block = 256 (warp w handles j = j0 + w)
// ---------------------------------------------------------------------------
__global__ __launch_bounds__(256)
void attn_main_kernel(const float4* __restrict__ key4,
                      const float4* __restrict__ value4,
                      float* __restrict__ out) {
    const int tid  = threadIdx.x;
    const int w    = tid >> 5;
    const int lane = tid & 31;
    const int bi   = blockIdx.x >> 3;          // (b*L + i), 0..127
    const int j0   = (blockIdx.x & 7) * G;     // j tile base
    const int j    = j0 + w;

    __shared__ float4 vbar_sh[G * 64];         // [jj][64 float4] = [jj][256 floats]

    // Qk for this (b,i): each lane holds 8 values as two float4
    const float4* qk4 = reinterpret_cast<const float4*>(g_Qk) + bi * 64;
    const float4 qk0 = qk4[lane];
    const float4 qk1 = qk4[32 + lane];

    const size_t base = (size_t)(bi * DL + j) * (DT * 64);   // in float4 units
    const float4* kp = key4 + base;

    // ---- Phase A: 32 scores (dot of length 256), butterfly-reduced ----
    float myscore = 0.f;
#pragma unroll 4
    for (int t = 0; t < DT; t++) {
        const float4 k0 = kp[t * 64 + lane];
        const float4 k1 = kp[t * 64 + 32 + lane];
        float s = k0.x * qk0.x + k0.y * qk0.y + k0.z * qk0.z + k0.w * qk0.w
                + k1.x * qk1.x + k1.y * qk1.y + k1.z * qk1.z + k1.w * qk1.w;
#pragma unroll
        for (int off = 16; off; off >>= 1)
            s += __shfl_xor_sync(0xffffffffu, s, off);
        myscore = (lane == t) ? s : myscore;   // lane t keeps score[t]
    }

    // ---- warp-local softmax over T=32 (one score per lane) ----
    float m = myscore;
#pragma unroll
    for (int off = 16; off; off >>= 1)
        m = fmaxf(m, __shfl_xor_sync(0xffffffffu, m, off));
    const float ex = __expf(myscore - m);
    float ssum = ex;
#pragma unroll
    for (int off = 16; off; off >>= 1)
        ssum += __shfl_xor_sync(0xffffffffu, ssum, off);
    const float a = ex / ssum;                  // attn[t = lane]

    // ---- Phase B: vbar[d] = sum_t attn[t] * value[t,d] ----
    const float4* vp = value4 + base;
    float4 acc0 = make_float4(0.f, 0.f, 0.f, 0.f);
    float4 acc1 = make_float4(0.f, 0.f, 0.f, 0.f);
#pragma unroll 4
    for (int t = 0; t < DT; t++) {
        const float at = __shfl_sync(0xffffffffu, a, t);
        const float4 v0 = vp[t * 64 + lane];
        const float4 v1 = vp[t * 64 + 32 + lane];
        acc0.x += at * v0.x; acc0.y += at * v0.y;
        acc0.z += at * v0.z; acc0.w += at * v0.w;
        acc1.x += at * v1.x; acc1.y += at * v1.y;
        acc1.z += at * v1.z; acc1.w += at * v1.w;
    }
    vbar_sh[w * 64 + lane]      = acc0;
    vbar_sh[w * 64 + 32 + lane] = acc1;
    __syncthreads();

    // ---- Phase C: out[j0+jj, f] = bcomb[f] + sum_d vbar[jj][d] * WcombT[d,f] ----
    const int f = tid;
    float acc[G];
    const float bc = g_bcomb[f];
#pragma unroll
    for (int jj = 0; jj < G; jj++) acc[jj] = bc;

    for (int d4 = 0; d4 < 64; d4++) {
        const float* wt = &g_WcombT[(size_t)(d4 * 4) * DD + f];  // coalesced over f
        const float w0 = wt[0];
        const float w1 = wt[DD];
        const float w2 = wt[2 * DD];
        const float w3 = wt[3 * DD];
#pragma unroll
        for (int jj = 0; jj < G; jj++) {
            const float4 v = vbar_sh[jj * 64 + d4];              // smem broadcast
            acc[jj] += v.x * w0 + v.y * w1 + v.z * w2 + v.w * w3;
        }
    }

    const size_t obase = (size_t)(bi * DL + j0) * DD + f;
#pragma unroll
    for (int jj = 0; jj < G; jj++)
        out[obase + (size_t)jj * DD] = acc[jj];
}

// ---------------------------------------------------------------------------
// Launch. Input order (metadata): key, value, query, Wk, bk, Wv, bv, Wq, bq, Wf, bf
// ---------------------------------------------------------------------------
extern "C" void kernel_launch(void* const* d_in, const int* in_sizes, int n_in,
                              void* d_out, int out_size) {
    const float* key   = (const float*)d_in[0];
    const float* value = (const float*)d_in[1];
    const float* query = (const float*)d_in[2];
    const float* Wk    = (const float*)d_in[3];
    // bk (d_in[4]) cancels under softmax — unused.
    const float* Wv    = (const float*)d_in[5];
    const float* bv    = (const float*)d_in[6];
    const float* Wq    = (const float*)d_in[7];
    const float* bq    = (const float*)d_in[8];
    const float* Wf    = (const float*)d_in[9];
    const float* bf    = (const float*)d_in[10];
    float* out = (float*)d_out;

    qk_kernel<<<DB * DL, DD>>>(query, Wq, bq, Wk);
    wcomb_kernel<<<dim3(8, 8), dim3(32, 32)>>>(Wv, Wf);
    bcomb_kernel<<<1, DD>>>(Wf, bv, bf);

    const int nblocks = DB * DL * DL / G;   // 1024
    attn_main_kernel<<<nblocks, 256>>>(
        reinterpret_cast<const float4*>(key),
        reinterpret_cast<const float4*>(value),
        out);
}

// round 2
// speedup vs baseline: 1.3713x; 1.3713x over previous
#include <cuda_runtime.h>

#define DB 2     // batch
#define DL 64    // L
#define DT 32    // T
#define DD 256   // D
#define G  8     // j-columns per block in the main kernel

// Scratch (device globals: no allocation allowed)
__device__ float g_Qk[DB * DL * DD];      // per (b,i): query @ (Wq^T Wk)/16 + bias-fold
__device__ float g_Wqk[DD * DD];          // Wqk[a,d] = (1/16) sum_e Wq[e,a]*Wk[e,d]
__device__ float g_bqk[DD];               // (1/16) sum_e bq[e]*Wk[e,d]
__device__ float g_WcombT[DD * DD];       // WcombT[d,f] = sum_e Wv[e,d]*Wf[f,e]
__device__ float g_bcomb[DD];             // bcomb[f] = sum_e Wf[f,e]*bv[e] + bf[f]

// ---------------------------------------------------------------------------
// Prologue 1: all weight-space precomputes in ONE kernel.
//   blocks 0..63   : WcombT tile (32x32 tiled GEMM)
//   blocks 64..127 : Wqk tile    (32x32 tiled GEMM)
//   block 128      : bqk + bcomb
// block = (32,32)
// ---------------------------------------------------------------------------
__global__ void weights_kernel(const float* __restrict__ Wq,
                               const float* __restrict__ Wk,
                               const float* __restrict__ Wv,
                               const float* __restrict__ Wf,
                               const float* __restrict__ bq,
                               const float* __restrict__ bv,
                               const float* __restrict__ bf) {
    const int tx = threadIdx.x, ty = threadIdx.y;
    const int blk = blockIdx.x;

    if (blk < 128) {
        __shared__ float As[32][33];
        __shared__ float Bs[32][33];
        const bool isWcomb = (blk < 64);
        const int b  = blk & 63;
        const int c0 = (b & 7) * 32;    // output col tile (f for Wcomb, d for Wqk)
        const int r0 = (b >> 3) * 32;   // output row tile (d for WcombT, a for Wqk)

        float acc = 0.f;
        for (int e0 = 0; e0 < DD; e0 += 32) {
            if (isWcomb) {
                As[ty][tx] = Wv[(size_t)(e0 + ty) * DD + r0 + tx];  // As[k][m]=Wv[e,d]
                Bs[ty][tx] = Wf[(size_t)(c0 + ty) * DD + e0 + tx];  // Bs[m][k]=Wf[f,e]
            } else {
                As[ty][tx] = Wq[(size_t)(e0 + ty) * DD + r0 + tx];  // As[k][m]=Wq[e,a]
                Bs[ty][tx] = Wk[(size_t)(e0 + ty) * DD + c0 + tx];  // Bs[k][n]=Wk[e,d]
            }
            __syncthreads();
            if (isWcomb) {
#pragma unroll
                for (int k = 0; k < 32; k++) acc += As[k][ty] * Bs[tx][k];
            } else {
#pragma unroll
                for (int k = 0; k < 32; k++) acc += As[k][ty] * Bs[k][tx];
            }
            __syncthreads();
        }
        if (isWcomb) g_WcombT[(size_t)(r0 + ty) * DD + c0 + tx] = acc;
        else         g_Wqk[(size_t)(r0 + ty) * DD + c0 + tx] = acc * 0.0625f;
    } else {
        // biases: 256 active threads
        const int t = ty * 32 + tx;
        if (t < DD) {
            float accq = 0.f;
#pragma unroll 8
            for (int e = 0; e < DD; e++) accq += bq[e] * Wk[(size_t)e * DD + t]; // coalesced
            g_bqk[t] = accq * 0.0625f;

            float accc = bf[t];
            const float* wf = Wf + (size_t)t * DD;
#pragma unroll 8
            for (int e = 0; e < DD; e++) accc += wf[e] * bv[e];
            g_bcomb[t] = accc;
        }
    }
}

// ---------------------------------------------------------------------------
// Prologue 2: Qk[bi,d] = sum_d0 query[bi,d0] * Wqk[d0,d] + bqk[d]
// grid = 128, block = 256, fully coalesced over d
// ---------------------------------------------------------------------------
__global__ void qk2_kernel(const float* __restrict__ query) {
    const int bi = blockIdx.x;
    const int d  = threadIdx.x;
    __shared__ float q[DD];
    q[d] = query[bi * DD + d];
    __syncthreads();

    float acc = g_bqk[d];
#pragma unroll 8
    for (int d0 = 0; d0 < DD; d0++) acc += q[d0] * g_Wqk[(size_t)d0 * DD + d];
    g_Qk[bi * DD + d] = acc;
}

// ---------------------------------------------------------------------------
// Main kernel: one streaming pass over key and value.
// Per warp (one j): Phase A computes per-lane partial scores for ALL 32 t
// (no cross-lane ops in the load loop -> max MLP), then a log2 fold-reduce
// (31 shfls total) lands score[t] in lane t. Softmax is warp-local; Phase B
// streams value; Phase C is the folded output GEMM from L2-resident WcombT.
// grid = B*L*L/G = 1024, block = 256
// ---------------------------------------------------------------------------
__global__ __launch_bounds__(256)
void attn_main_kernel(const float4* __restrict__ key4,
                      const float4* __restrict__ value4,
                      float* __restrict__ out) {
    const int tid  = threadIdx.x;
    const int w    = tid >> 5;
    const int lane = tid & 31;
    const int bi   = blockIdx.x >> 3;          // (b*L + i), 0..127
    const int j0   = (blockIdx.x & 7) * G;     // j tile base
    const int j    = j0 + w;

    __shared__ float4 vbar_sh[G * 64];         // [jj][64 float4]

    const float4* qk4 = reinterpret_cast<const float4*>(g_Qk) + bi * 64;
    const float4 qk0 = qk4[lane];
    const float4 qk1 = qk4[32 + lane];

    const size_t base = (size_t)(bi * DL + j) * (DT * 64);   // float4 units
    const float4* kp = key4 + base;

    // ---- Phase A: per-lane partial dots over this lane's 8-float d-slice ----
    float st[16];
#pragma unroll
    for (int t = 0; t < 16; t++) {
        const float4 k0 = kp[t * 64 + lane];
        const float4 k1 = kp[t * 64 + 32 + lane];
        st[t] = k0.x * qk0.x + k0.y * qk0.y + k0.z * qk0.z + k0.w * qk0.w
              + k1.x * qk1.x + k1.y * qk1.y + k1.z * qk1.z + k1.w * qk1.w;
    }
    // second half of t, with the o=16 fold step done incrementally
    const bool hi16 = (lane & 16) != 0;
#pragma unroll
    for (int t = 16; t < 32; t++) {
        const float4 k0 = kp[t * 64 + lane];
        const float4 k1 = kp[t * 64 + 32 + lane];
        const float s = k0.x * qk0.x + k0.y * qk0.y + k0.z * qk0.z + k0.w * qk0.w
                      + k1.x * qk1.x + k1.y * qk1.y + k1.z * qk1.z + k1.w * qk1.w;
        const float send = hi16 ? st[t - 16] : s;
        const float recv = __shfl_xor_sync(0xffffffffu, send, 16);
        st[t - 16] = (hi16 ? s : st[t - 16]) + recv;
    }
    // remaining fold steps: o = 8,4,2,1 ; lane ends with score[t = lane]
#pragma unroll
    for (int o = 8; o >= 1; o >>= 1) {
        const bool hi = (lane & o) != 0;
#pragma unroll
        for (int i = 0; i < o; i++) {
            const float send = hi ? st[i] : st[i + o];
            const float recv = __shfl_xor_sync(0xffffffffu, send, o);
            st[i] = (hi ? st[i + o] : st[i]) + recv;
        }
    }
    const float myscore = st[0];

    // ---- warp-local softmax over T=32 ----
    float m = myscore;
#pragma unroll
    for (int off = 16; off; off >>= 1)
        m = fmaxf(m, __shfl_xor_sync(0xffffffffu, m, off));
    const float ex = __expf(myscore - m);
    float ssum = ex;
#pragma unroll
    for (int off = 16; off; off >>= 1)
        ssum += __shfl_xor_sync(0xffffffffu, ssum, off);
    const float a = ex / ssum;                  // attn[t = lane]

    // ---- Phase B: vbar[d] = sum_t attn[t] * value[t,d] ----
    const float4* vp = value4 + base;
    float4 acc0 = make_float4(0.f, 0.f, 0.f, 0.f);
    float4 acc1 = make_float4(0.f, 0.f, 0.f, 0.f);
#pragma unroll
    for (int t = 0; t < DT; t++) {
        const float at = __shfl_sync(0xffffffffu, a, t);
        const float4 v0 = vp[t * 64 + lane];
        const float4 v1 = vp[t * 64 + 32 + lane];
        acc0.x += at * v0.x; acc0.y += at * v0.y;
        acc0.z += at * v0.z; acc0.w += at * v0.w;
        acc1.x += at * v1.x; acc1.y += at * v1.y;
        acc1.z += at * v1.z; acc1.w += at * v1.w;
    }
    vbar_sh[w * 64 + lane]      = acc0;
    vbar_sh[w * 64 + 32 + lane] = acc1;
    __syncthreads();

    // ---- Phase C: out[j0+jj, f] = bcomb[f] + sum_d vbar[jj][d]*WcombT[d,f] ----
    const int f = tid;
    float acc[G];
    const float bc = g_bcomb[f];
#pragma unroll
    for (int jj = 0; jj < G; jj++) acc[jj] = bc;

    for (int d4 = 0; d4 < 64; d4++) {
        const float* wt = &g_WcombT[(size_t)(d4 * 4) * DD + f];  // coalesced over f
        const float w0 = wt[0];
        const float w1 = wt[DD];
        const float w2 = wt[2 * DD];
        const float w3 = wt[3 * DD];
#pragma unroll
        for (int jj = 0; jj < G; jj++) {
            const float4 v = vbar_sh[jj * 64 + d4];
            acc[jj] += v.x * w0 + v.y * w1 + v.z * w2 + v.w * w3;
        }
    }

    const size_t obase = (size_t)(bi * DL + j0) * DD + f;
#pragma unroll
    for (int jj = 0; jj < G; jj++)
        out[obase + (size_t)jj * DD] = acc[jj];
}

// ---------------------------------------------------------------------------
// Launch. Input order: key, value, query, Wk, bk, Wv, bv, Wq, bq, Wf, bf
// ---------------------------------------------------------------------------
extern "C" void kernel_launch(void* const* d_in, const int* in_sizes, int n_in,
                              void* d_out, int out_size) {
    const float* key   = (const float*)d_in[0];
    const float* value = (const float*)d_in[1];
    const float* query = (const float*)d_in[2];
    const float* Wk    = (const float*)d_in[3];
    // bk (d_in[4]) cancels under softmax — unused.
    const float* Wv    = (const float*)d_in[5];
    const float* bv    = (const float*)d_in[6];
    const float* Wq    = (const float*)d_in[7];
    const float* bq    = (const float*)d_in[8];
    const float* Wf    = (const float*)d_in[9];
    const float* bf    = (const float*)d_in[10];
    float* out = (float*)d_out;

    weights_kernel<<<129, dim3(32, 32)>>>(Wq, Wk, Wv, Wf, bq, bv, bf);
    qk2_kernel<<<DB * DL, DD>>>(query);

    const int nblocks = DB * DL * DL / G;   // 1024
    attn_main_kernel<<<nblocks, 256>>>(
        reinterpret_cast<const float4*>(key),
        reinterpret_cast<const float4*>(value),
        out);
}

// round 3
// speedup vs baseline: 1.5286x; 1.1147x over previous
#include <cuda_runtime.h>

#define DB 2     // batch
#define DL 64    // L
#define DT 32    // T
#define DD 256   // D
#define G  8     // j-columns per block in the main kernel

// Scratch (device globals: no allocation allowed)
__device__ float g_Qk[DB * DL * DD];      // per (b,i): ((q@Wq^T+bq)/16)@Wk
__device__ float g_WcombT[DD * DD];       // WcombT[d,f] = sum_e Wv[e,d]*Wf[f,e]
__device__ float g_bcomb[DD];             // bcomb[f] = sum_e Wf[f,e]*bv[e] + bf[f]

// ---------------------------------------------------------------------------
// Single prologue kernel, block = (32,32) = 1024 threads.
//   blk 0..63    : WcombT 32x32 tile, double-buffered k-slabs
//   blk 64..191  : Qk for bi = blk-64 (two chained matvecs, fully coalesced)
//   blk 192      : bcomb
// ---------------------------------------------------------------------------
__global__ void prologue_kernel(const float* __restrict__ query,
                                const float* __restrict__ Wq,
                                const float* __restrict__ bq,
                                const float* __restrict__ Wk,
                                const float* __restrict__ Wv,
                                const float* __restrict__ bv,
                                const float* __restrict__ Wf,
                                const float* __restrict__ bf) {
    const int tx = threadIdx.x, ty = threadIdx.y;
    const int tid = ty * 32 + tx;
    const int blk = blockIdx.x;

    if (blk < 64) {
        // ---- WcombT[d,f] = sum_e Wv[e,d] * Wf[f,e], tile (d0,f0), dbl-buffered
        __shared__ float Av[2][32][33];   // Av[buf][k][m] = Wv[e0+k, d0+m]
        __shared__ float Bf[2][32][33];   // Bf[buf][m][k] = Wf[f0+m, e0+k]
        const int f0 = (blk & 7) * 32;
        const int d0 = (blk >> 3) * 32;

        Av[0][ty][tx] = Wv[(size_t)ty * DD + d0 + tx];
        Bf[0][ty][tx] = Wf[(size_t)(f0 + ty) * DD + tx];
        __syncthreads();

        float acc = 0.f;
#pragma unroll
        for (int s = 0; s < 8; s++) {
            const int cur = s & 1;
            if (s < 7) {
                const int e0 = (s + 1) * 32;
                Av[cur ^ 1][ty][tx] = Wv[(size_t)(e0 + ty) * DD + d0 + tx];
                Bf[cur ^ 1][ty][tx] = Wf[(size_t)(f0 + ty) * DD + e0 + tx];
            }
#pragma unroll
            for (int k = 0; k < 32; k++) acc += Av[cur][k][ty] * Bf[cur][tx][k];
            __syncthreads();
        }
        g_WcombT[(size_t)(d0 + ty) * DD + f0 + tx] = acc;

    } else if (blk < 192) {
        // ---- Qk[bi,:] : Q[e] = (q . Wq[e,:] + bq[e])/16 ; Qk[d] = sum_e Q[e]*Wk[e,d]
        const int bi = blk - 64;
        __shared__ float q[DD];
        __shared__ float Qs[DD];
        __shared__ float part[4][DD];

        if (tid < DD) q[tid] = query[bi * DD + tid];
        __syncthreads();

        // warp ty handles e = ty*8 .. ty*8+7 ; lane tx sums strided (coalesced)
#pragma unroll
        for (int i = 0; i < 8; i++) {
            const int e = ty * 8 + i;
            const float* wq = Wq + (size_t)e * DD;
            float p = 0.f;
#pragma unroll
            for (int c = 0; c < 8; c++) p += q[tx + 32 * c] * wq[tx + 32 * c];
#pragma unroll
            for (int off = 16; off; off >>= 1)
                p += __shfl_xor_sync(0xffffffffu, p, off);
            if (tx == 0) Qs[e] = (p + bq[e]) * 0.0625f;
        }
        __syncthreads();

        // Qk[d] : 4 e-quarters in parallel, coalesced over d
        const int quarter = ty >> 3;
        const int d = tx + (ty & 7) * 32;
        const int e0 = quarter * 64;
        float acc = 0.f;
#pragma unroll 8
        for (int e = 0; e < 64; e++)
            acc += Qs[e0 + e] * Wk[(size_t)(e0 + e) * DD + d];
        part[quarter][d] = acc;
        __syncthreads();
        if (tid < DD)
            g_Qk[bi * DD + tid] = part[0][tid] + part[1][tid] + part[2][tid] + part[3][tid];

    } else {
        // ---- bcomb[f] = sum_e Wf[f,e]*bv[e] + bf[f] ; warp ty handles f=ty*8..+7
        __shared__ float bvs[DD];
        if (tid < DD) bvs[tid] = bv[tid];
        __syncthreads();
#pragma unroll
        for (int i = 0; i < 8; i++) {
            const int f = ty * 8 + i;
            const float* wf = Wf + (size_t)f * DD;
            float p = 0.f;
#pragma unroll
            for (int c = 0; c < 8; c++) p += bvs[tx + 32 * c] * wf[tx + 32 * c];
#pragma unroll
            for (int off = 16; off; off >>= 1)
                p += __shfl_xor_sync(0xffffffffu, p, off);
            if (tx == 0) g_bcomb[f] = p + bf[f];
        }
    }
}

// ---------------------------------------------------------------------------
// Main kernel: one streaming pass over key and value.
// __launch_bounds__(256, 7): 7 blocks/SM -> 1036 >= 1024 grid = ONE wave,
// killing the 136-block straggler tail seen at 6 blocks/SM.
// grid = B*L*L/G = 1024, block = 256 (warp w owns j = j0 + w)
// ---------------------------------------------------------------------------
__global__ __launch_bounds__(256, 7)
void attn_main_kernel(const float4* __restrict__ key4,
                      const float4* __restrict__ value4,
                      float* __restrict__ out) {
    const int tid  = threadIdx.x;
    const int w    = tid >> 5;
    const int lane = tid & 31;
    const int bi   = blockIdx.x >> 3;          // (b*L + i), 0..127
    const int j0   = (blockIdx.x & 7) * G;     // j tile base
    const int j    = j0 + w;

    __shared__ float4 vbar_sh[G * 64];         // [jj][64 float4]

    const float4* qk4 = reinterpret_cast<const float4*>(g_Qk) + bi * 64;
    const float4 qk0 = qk4[lane];
    const float4 qk1 = qk4[32 + lane];

    const size_t base = (size_t)(bi * DL + j) * (DT * 64);   // float4 units
    const float4* kp = key4 + base;

    // ---- Phase A: per-lane partial dots, no cross-lane ops in load loop ----
    float st[16];
#pragma unroll
    for (int t = 0; t < 16; t++) {
        const float4 k0 = kp[t * 64 + lane];
        const float4 k1 = kp[t * 64 + 32 + lane];
        st[t] = k0.x * qk0.x + k0.y * qk0.y + k0.z * qk0.z + k0.w * qk0.w
              + k1.x * qk1.x + k1.y * qk1.y + k1.z * qk1.z + k1.w * qk1.w;
    }
    const bool hi16 = (lane & 16) != 0;
#pragma unroll
    for (int t = 16; t < 32; t++) {
        const float4 k0 = kp[t * 64 + lane];
        const float4 k1 = kp[t * 64 + 32 + lane];
        const float s = k0.x * qk0.x + k0.y * qk0.y + k0.z * qk0.z + k0.w * qk0.w
                      + k1.x * qk1.x + k1.y * qk1.y + k1.z * qk1.z + k1.w * qk1.w;
        const float send = hi16 ? st[t - 16] : s;
        const float recv = __shfl_xor_sync(0xffffffffu, send, 16);
        st[t - 16] = (hi16 ? s : st[t - 16]) + recv;
    }
#pragma unroll
    for (int o = 8; o >= 1; o >>= 1) {
        const bool hi = (lane & o) != 0;
#pragma unroll
        for (int i = 0; i < o; i++) {
            const float send = hi ? st[i] : st[i + o];
            const float recv = __shfl_xor_sync(0xffffffffu, send, o);
            st[i] = (hi ? st[i + o] : st[i]) + recv;
        }
    }
    const float myscore = st[0];

    // ---- warp-local softmax over T=32 ----
    float m = myscore;
#pragma unroll
    for (int off = 16; off; off >>= 1)
        m = fmaxf(m, __shfl_xor_sync(0xffffffffu, m, off));
    const float ex = __expf(myscore - m);
    float ssum = ex;
#pragma unroll
    for (int off = 16; off; off >>= 1)
        ssum += __shfl_xor_sync(0xffffffffu, ssum, off);
    const float a = ex / ssum;                  // attn[t = lane]

    // ---- Phase B: vbar[d] = sum_t attn[t] * value[t,d] ----
    const float4* vp = value4 + base;
    float4 acc0 = make_float4(0.f, 0.f, 0.f, 0.f);
    float4 acc1 = make_float4(0.f, 0.f, 0.f, 0.f);
#pragma unroll
    for (int t = 0; t < DT; t++) {
        const float at = __shfl_sync(0xffffffffu, a, t);
        const float4 v0 = vp[t * 64 + lane];
        const float4 v1 = vp[t * 64 + 32 + lane];
        acc0.x += at * v0.x; acc0.y += at * v0.y;
        acc0.z += at * v0.z; acc0.w += at * v0.w;
        acc1.x += at * v1.x; acc1.y += at * v1.y;
        acc1.z += at * v1.z; acc1.w += at * v1.w;
    }
    vbar_sh[w * 64 + lane]      = acc0;
    vbar_sh[w * 64 + 32 + lane] = acc1;
    __syncthreads();

    // ---- Phase C: out[j0+jj, f] = bcomb[f] + sum_d vbar[jj][d]*WcombT[d,f] ----
    const int f = tid;
    float acc[G];
    const float bc = g_bcomb[f];
#pragma unroll
    for (int jj = 0; jj < G; jj++) acc[jj] = bc;

#pragma unroll 4
    for (int d4 = 0; d4 < 64; d4++) {
        const float* wt = &g_WcombT[(size_t)(d4 * 4) * DD + f];  // coalesced over f
        const float w0 = wt[0];
        const float w1 = wt[DD];
        const float w2 = wt[2 * DD];
        const float w3 = wt[3 * DD];
#pragma unroll
        for (int jj = 0; jj < G; jj++) {
            const float4 v = vbar_sh[jj * 64 + d4];
            acc[jj] += v.x * w0 + v.y * w1 + v.z * w2 + v.w * w3;
        }
    }

    const size_t obase = (size_t)(bi * DL + j0) * DD + f;
#pragma unroll
    for (int jj = 0; jj < G; jj++)
        out[obase + (size_t)jj * DD] = acc[jj];
}

// ---------------------------------------------------------------------------
// Launch. Input order: key, value, query, Wk, bk, Wv, bv, Wq, bq, Wf, bf
// ---------------------------------------------------------------------------
extern "C" void kernel_launch(void* const* d_in, const int* in_sizes, int n_in,
                              void* d_out, int out_size) {
    const float* key   = (const float*)d_in[0];
    const float* value = (const float*)d_in[1];
    const float* query = (const float*)d_in[2];
    const float* Wk    = (const float*)d_in[3];
    // bk (d_in[4]) cancels under softmax — unused.
    const float* Wv    = (const float*)d_in[5];
    const float* bv    = (const float*)d_in[6];
    const float* Wq    = (const float*)d_in[7];
    const float* bq    = (const float*)d_in[8];
    const float* Wf    = (const float*)d_in[9];
    const float* bf    = (const float*)d_in[10];
    float* out = (float*)d_out;

    prologue_kernel<<<193, dim3(32, 32)>>>(query, Wq, bq, Wk, Wv, bv, Wf, bf);

    const int nblocks = DB * DL * DL / G;   // 1024
    attn_main_kernel<<<nblocks, 256>>>(
        reinterpret_cast<const float4*>(key),
        reinterpret_cast<const float4*>(value),
        out);
}

// round 4
// speedup vs baseline: 1.9164x; 1.2537x over previous
#include <cuda_runtime.h>

#define DB 2     // batch
#define DL 64    // L
#define DT 32    // T
#define DD 256   // D
#define G  8     // j-columns per tile
#define NTILES (DB * DL * DL / G)   // 1024

// Scratch (device globals: no allocation allowed)
__device__ float g_Qk[DB * DL * DD];      // per (b,i): ((q@Wq^T+bq)/16)@Wk
__device__ float g_WcombT[DD * DD];       // WcombT[d,f] = sum_e Wv[e,d]*Wf[f,e]
__device__ float g_bcomb[DD];             // bcomb[f] = sum_e Wf[f,e]*bv[e] + bf[f]
__device__ int   g_ticket;                // dynamic tile ticket

// ---------------------------------------------------------------------------
// Single prologue kernel, block = (32,32) = 1024 threads.
//   blk 0..63    : WcombT 32x32 tile, double-buffered k-slabs
//   blk 64..191  : Qk for bi = blk-64 (two chained matvecs, fully coalesced)
//   blk 192      : bcomb + ticket reset
// ---------------------------------------------------------------------------
__global__ void prologue_kernel(const float* __restrict__ query,
                                const float* __restrict__ Wq,
                                const float* __restrict__ bq,
                                const float* __restrict__ Wk,
                                const float* __restrict__ Wv,
                                const float* __restrict__ bv,
                                const float* __restrict__ Wf,
                                const float* __restrict__ bf) {
    const int tx = threadIdx.x, ty = threadIdx.y;
    const int tid = ty * 32 + tx;
    const int blk = blockIdx.x;

    if (blk < 64) {
        __shared__ float Av[2][32][33];   // Av[buf][k][m] = Wv[e0+k, d0+m]
        __shared__ float Bf[2][32][33];   // Bf[buf][m][k] = Wf[f0+m, e0+k]
        const int f0 = (blk & 7) * 32;
        const int d0 = (blk >> 3) * 32;

        Av[0][ty][tx] = Wv[(size_t)ty * DD + d0 + tx];
        Bf[0][ty][tx] = Wf[(size_t)(f0 + ty) * DD + tx];
        __syncthreads();

        float acc = 0.f;
#pragma unroll
        for (int s = 0; s < 8; s++) {
            const int cur = s & 1;
            if (s < 7) {
                const int e0 = (s + 1) * 32;
                Av[cur ^ 1][ty][tx] = Wv[(size_t)(e0 + ty) * DD + d0 + tx];
                Bf[cur ^ 1][ty][tx] = Wf[(size_t)(f0 + ty) * DD + e0 + tx];
            }
#pragma unroll
            for (int k = 0; k < 32; k++) acc += Av[cur][k][ty] * Bf[cur][tx][k];
            __syncthreads();
        }
        g_WcombT[(size_t)(d0 + ty) * DD + f0 + tx] = acc;

    } else if (blk < 192) {
        const int bi = blk - 64;
        __shared__ float q[DD];
        __shared__ float Qs[DD];
        __shared__ float part[4][DD];

        if (tid < DD) q[tid] = query[bi * DD + tid];
        __syncthreads();

#pragma unroll
        for (int i = 0; i < 8; i++) {
            const int e = ty * 8 + i;
            const float* wq = Wq + (size_t)e * DD;
            float p = 0.f;
#pragma unroll
            for (int c = 0; c < 8; c++) p += q[tx + 32 * c] * wq[tx + 32 * c];
#pragma unroll
            for (int off = 16; off; off >>= 1)
                p += __shfl_xor_sync(0xffffffffu, p, off);
            if (tx == 0) Qs[e] = (p + bq[e]) * 0.0625f;
        }
        __syncthreads();

        const int quarter = ty >> 3;
        const int d = tx + (ty & 7) * 32;
        const int e0 = quarter * 64;
        float acc = 0.f;
#pragma unroll 8
        for (int e = 0; e < 64; e++)
            acc += Qs[e0 + e] * Wk[(size_t)(e0 + e) * DD + d];
        part[quarter][d] = acc;
        __syncthreads();
        if (tid < DD)
            g_Qk[bi * DD + tid] = part[0][tid] + part[1][tid] + part[2][tid] + part[3][tid];

    } else {
        if (tid == 0) g_ticket = 0;
        __shared__ float bvs[DD];
        if (tid < DD) bvs[tid] = bv[tid];
        __syncthreads();
#pragma unroll
        for (int i = 0; i < 8; i++) {
            const int f = ty * 8 + i;
            const float* wf = Wf + (size_t)f * DD;
            float p = 0.f;
#pragma unroll
            for (int c = 0; c < 8; c++) p += bvs[tx + 32 * c] * wf[tx + 32 * c];
#pragma unroll
            for (int off = 16; off; off >>= 1)
                p += __shfl_xor_sync(0xffffffffu, p, off);
            if (tx == 0) g_bcomb[f] = p + bf[f];
        }
    }
}

// ---------------------------------------------------------------------------
// Main kernel: persistent blocks pulling tiles from a global ticket.
// grid = 740 (<=5 blocks/SM -> always one resident wave), block = 256.
// No register cap -> no spills; dynamic tiles -> no static wave tail.
// Per tile: warp w owns j = j0 + w.
// ---------------------------------------------------------------------------
__global__ __launch_bounds__(256)
void attn_main_kernel(const float4* __restrict__ key4,
                      const float4* __restrict__ value4,
                      float* __restrict__ out) {
    const int tid  = threadIdx.x;
    const int w    = tid >> 5;
    const int lane = tid & 31;

    __shared__ int    s_tile;
    __shared__ float4 vbar_sh[G * 64];         // [jj][64 float4]

    for (;;) {
        __syncthreads();                        // vbar_sh reuse + s_tile safety
        if (tid == 0) s_tile = atomicAdd(&g_ticket, 1);
        __syncthreads();
        const int tile = s_tile;
        if (tile >= NTILES) return;

        const int bi = tile >> 3;               // (b*L + i), 0..127
        const int j0 = (tile & 7) * G;
        const int j  = j0 + w;

        const float4* qk4 = reinterpret_cast<const float4*>(g_Qk) + bi * 64;
        const float4 qk0 = qk4[lane];
        const float4 qk1 = qk4[32 + lane];

        const size_t base = (size_t)(bi * DL + j) * (DT * 64);   // float4 units
        const float4* kp = key4 + base;
        const float4* vp = value4 + base;

        // ---- Phase A: per-lane partial dots (streaming loads, max MLP) ----
        float st[16];
#pragma unroll
        for (int t = 0; t < 16; t++) {
            const float4 k0 = __ldcs(kp + t * 64 + lane);
            const float4 k1 = __ldcs(kp + t * 64 + 32 + lane);
            st[t] = k0.x * qk0.x + k0.y * qk0.y + k0.z * qk0.z + k0.w * qk0.w
                  + k1.x * qk1.x + k1.y * qk1.y + k1.z * qk1.z + k1.w * qk1.w;
        }
        const bool hi16 = (lane & 16) != 0;
#pragma unroll
        for (int t = 16; t < 32; t++) {
            const float4 k0 = __ldcs(kp + t * 64 + lane);
            const float4 k1 = __ldcs(kp + t * 64 + 32 + lane);
            const float s = k0.x * qk0.x + k0.y * qk0.y + k0.z * qk0.z + k0.w * qk0.w
                          + k1.x * qk1.x + k1.y * qk1.y + k1.z * qk1.z + k1.w * qk1.w;
            const float send = hi16 ? st[t - 16] : s;
            const float recv = __shfl_xor_sync(0xffffffffu, send, 16);
            st[t - 16] = (hi16 ? s : st[t - 16]) + recv;
        }
#pragma unroll
        for (int o = 8; o >= 1; o >>= 1) {
            const bool hi = (lane & o) != 0;
#pragma unroll
            for (int i = 0; i < o; i++) {
                const float send = hi ? st[i] : st[i + o];
                const float recv = __shfl_xor_sync(0xffffffffu, send, o);
                st[i] = (hi ? st[i + o] : st[i]) + recv;
            }
        }
        const float myscore = st[0];            // score[t = lane]

        // Prefetch value t=0,1 before the softmax dependency chain
        const float4 pv00 = __ldcs(vp + lane);
        const float4 pv01 = __ldcs(vp + 32 + lane);
        const float4 pv10 = __ldcs(vp + 64 + lane);
        const float4 pv11 = __ldcs(vp + 96 + lane);

        // ---- warp-local softmax over T=32 ----
        float m = myscore;
#pragma unroll
        for (int off = 16; off; off >>= 1)
            m = fmaxf(m, __shfl_xor_sync(0xffffffffu, m, off));
        const float ex = __expf(myscore - m);
        float ssum = ex;
#pragma unroll
        for (int off = 16; off; off >>= 1)
            ssum += __shfl_xor_sync(0xffffffffu, ssum, off);
        const float a = ex / ssum;              // attn[t = lane]

        // ---- Phase B: vbar[d] = sum_t attn[t] * value[t,d] ----
        float4 acc0, acc1;
        {
            const float a0 = __shfl_sync(0xffffffffu, a, 0);
            const float a1 = __shfl_sync(0xffffffffu, a, 1);
            acc0.x = a0 * pv00.x + a1 * pv10.x;
            acc0.y = a0 * pv00.y + a1 * pv10.y;
            acc0.z = a0 * pv00.z + a1 * pv10.z;
            acc0.w = a0 * pv00.w + a1 * pv10.w;
            acc1.x = a0 * pv01.x + a1 * pv11.x;
            acc1.y = a0 * pv01.y + a1 * pv11.y;
            acc1.z = a0 * pv01.z + a1 * pv11.z;
            acc1.w = a0 * pv01.w + a1 * pv11.w;
        }
#pragma unroll
        for (int t = 2; t < DT; t++) {
            const float at = __shfl_sync(0xffffffffu, a, t);
            const float4 v0 = __ldcs(vp + t * 64 + lane);
            const float4 v1 = __ldcs(vp + t * 64 + 32 + lane);
            acc0.x += at * v0.x; acc0.y += at * v0.y;
            acc0.z += at * v0.z; acc0.w += at * v0.w;
            acc1.x += at * v1.x; acc1.y += at * v1.y;
            acc1.z += at * v1.z; acc1.w += at * v1.w;
        }
        vbar_sh[w * 64 + lane]      = acc0;
        vbar_sh[w * 64 + 32 + lane] = acc1;
        __syncthreads();

        // ---- Phase C: out[j0+jj, f] = bcomb[f] + sum_d vbar[jj][d]*WcombT[d,f] ----
        const int f = tid;
        float acc[G];
        const float bc = g_bcomb[f];
#pragma unroll
        for (int jj = 0; jj < G; jj++) acc[jj] = bc;

#pragma unroll 4
        for (int d4 = 0; d4 < 64; d4++) {
            const float* wt = &g_WcombT[(size_t)(d4 * 4) * DD + f];  // coalesced over f
            const float w0 = wt[0];
            const float w1 = wt[DD];
            const float w2 = wt[2 * DD];
            const float w3 = wt[3 * DD];
#pragma unroll
            for (int jj = 0; jj < G; jj++) {
                const float4 v = vbar_sh[jj * 64 + d4];
                acc[jj] += v.x * w0 + v.y * w1 + v.z * w2 + v.w * w3;
            }
        }

        const size_t obase = (size_t)(bi * DL + j0) * DD + f;
#pragma unroll
        for (int jj = 0; jj < G; jj++)
            out[obase + (size_t)jj * DD] = acc[jj];
    }
}

// ---------------------------------------------------------------------------
// Launch. Input order: key, value, query, Wk, bk, Wv, bv, Wq, bq, Wf, bf
// ---------------------------------------------------------------------------
extern "C" void kernel_launch(void* const* d_in, const int* in_sizes, int n_in,
                              void* d_out, int out_size) {
    const float* key   = (const float*)d_in[0];
    const float* value = (const float*)d_in[1];
    const float* query = (const float*)d_in[2];
    const float* Wk    = (const float*)d_in[3];
    // bk (d_in[4]) cancels under softmax — unused.
    const float* Wv    = (const float*)d_in[5];
    const float* bv    = (const float*)d_in[6];
    const float* Wq    = (const float*)d_in[7];
    const float* bq    = (const float*)d_in[8];
    const float* Wf    = (const float*)d_in[9];
    const float* bf    = (const float*)d_in[10];
    float* out = (float*)d_out;

    prologue_kernel<<<193, dim3(32, 32)>>>(query, Wq, bq, Wk, Wv, bv, Wf, bf);

    attn_main_kernel<<<740, 256>>>(
        reinterpret_cast<const float4*>(key),
        reinterpret_cast<const float4*>(value),
        out);
}

// round 5
// speedup vs baseline: 2.0608x; 1.0754x over previous
#include <cuda_runtime.h>

#define DB 2     // batch
#define DL 64    // L
#define DT 32    // T
#define DD 256   // D
#define G  8     // j-columns per tile
#define NTILES (DB * DL * DL / G)   // 1024

// Scratch (device globals: no allocation allowed)
__device__ float g_Qk[DB * DL * DD];      // per (b,i): ((q@Wq^T+bq)/16)@Wk
__device__ float g_WcombT[DD * DD];       // WcombT[d,f] = sum_e Wv[e,d]*Wf[f,e]
__device__ float g_bcomb[DD];             // bcomb[f] = sum_e Wf[f,e]*bv[e] + bf[f]
__device__ int   g_ticket;                // dynamic tile ticket

// ---------------------------------------------------------------------------
// Single prologue kernel, block = (32,32) = 1024 threads.
// ---------------------------------------------------------------------------
__global__ void prologue_kernel(const float* __restrict__ query,
                                const float* __restrict__ Wq,
                                const float* __restrict__ bq,
                                const float* __restrict__ Wk,
                                const float* __restrict__ Wv,
                                const float* __restrict__ bv,
                                const float* __restrict__ Wf,
                                const float* __restrict__ bf) {
    const int tx = threadIdx.x, ty = threadIdx.y;
    const int tid = ty * 32 + tx;
    const int blk = blockIdx.x;

    if (blk < 64) {
        __shared__ float Av[2][32][33];   // Av[buf][k][m] = Wv[e0+k, d0+m]
        __shared__ float Bf[2][32][33];   // Bf[buf][m][k] = Wf[f0+m, e0+k]
        const int f0 = (blk & 7) * 32;
        const int d0 = (blk >> 3) * 32;

        Av[0][ty][tx] = Wv[(size_t)ty * DD + d0 + tx];
        Bf[0][ty][tx] = Wf[(size_t)(f0 + ty) * DD + tx];
        __syncthreads();

        float acc = 0.f;
#pragma unroll
        for (int s = 0; s < 8; s++) {
            const int cur = s & 1;
            if (s < 7) {
                const int e0 = (s + 1) * 32;
                Av[cur ^ 1][ty][tx] = Wv[(size_t)(e0 + ty) * DD + d0 + tx];
                Bf[cur ^ 1][ty][tx] = Wf[(size_t)(f0 + ty) * DD + e0 + tx];
            }
#pragma unroll
            for (int k = 0; k < 32; k++) acc += Av[cur][k][ty] * Bf[cur][tx][k];
            __syncthreads();
        }
        g_WcombT[(size_t)(d0 + ty) * DD + f0 + tx] = acc;

    } else if (blk < 192) {
        const int bi = blk - 64;
        __shared__ float q[DD];
        __shared__ float Qs[DD];
        __shared__ float part[4][DD];

        if (tid < DD) q[tid] = query[bi * DD + tid];
        __syncthreads();

#pragma unroll
        for (int i = 0; i < 8; i++) {
            const int e = ty * 8 + i;
            const float* wq = Wq + (size_t)e * DD;
            float p = 0.f;
#pragma unroll
            for (int c = 0; c < 8; c++) p += q[tx + 32 * c] * wq[tx + 32 * c];
#pragma unroll
            for (int off = 16; off; off >>= 1)
                p += __shfl_xor_sync(0xffffffffu, p, off);
            if (tx == 0) Qs[e] = (p + bq[e]) * 0.0625f;
        }
        __syncthreads();

        const int quarter = ty >> 3;
        const int d = tx + (ty & 7) * 32;
        const int e0 = quarter * 64;
        float acc = 0.f;
#pragma unroll 8
        for (int e = 0; e < 64; e++)
            acc += Qs[e0 + e] * Wk[(size_t)(e0 + e) * DD + d];
        part[quarter][d] = acc;
        __syncthreads();
        if (tid < DD)
            g_Qk[bi * DD + tid] = part[0][tid] + part[1][tid] + part[2][tid] + part[3][tid];

    } else {
        if (tid == 0) g_ticket = 0;
        __shared__ float bvs[DD];
        if (tid < DD) bvs[tid] = bv[tid];
        __syncthreads();
#pragma unroll
        for (int i = 0; i < 8; i++) {
            const int f = ty * 8 + i;
            const float* wf = Wf + (size_t)f * DD;
            float p = 0.f;
#pragma unroll
            for (int c = 0; c < 8; c++) p += bvs[tx + 32 * c] * wf[tx + 32 * c];
#pragma unroll
            for (int off = 16; off; off >>= 1)
                p += __shfl_xor_sync(0xffffffffu, p, off);
            if (tx == 0) g_bcomb[f] = p + bf[f];
        }
    }
}

// ---------------------------------------------------------------------------
// Phase-A helpers: eager binary-tree score fold (bit-reversed t order).
// ---------------------------------------------------------------------------
__device__ __forceinline__ float fold2(float x, float y, int o, int lane) {
    // x covers t-set S, y covers S+o ; result covers union, bit(o) of lane selects
    const bool hi = (lane & o) != 0;
    const float send = hi ? x : y;
    const float recv = __shfl_xor_sync(0xffffffffu, send, o);
    return (hi ? y : x) + recv;
}

__device__ __forceinline__ float score_pair(const float4* __restrict__ kp,
                                            int lane,
                                            const float4 qk0, const float4 qk1,
                                            int t) {
    // partial dots for t and t+16, folded at o=16
    const float4 a0 = __ldcs(kp + t * 64 + lane);
    const float4 a1 = __ldcs(kp + t * 64 + 32 + lane);
    const float4 b0 = __ldcs(kp + (t + 16) * 64 + lane);
    const float4 b1 = __ldcs(kp + (t + 16) * 64 + 32 + lane);
    const float sa = a0.x * qk0.x + a0.y * qk0.y + a0.z * qk0.z + a0.w * qk0.w
                   + a1.x * qk1.x + a1.y * qk1.y + a1.z * qk1.z + a1.w * qk1.w;
    const float sb = b0.x * qk0.x + b0.y * qk0.y + b0.z * qk0.z + b0.w * qk0.w
                   + b1.x * qk1.x + b1.y * qk1.y + b1.z * qk1.z + b1.w * qk1.w;
    return fold2(sa, sb, 16, lane);
}

// ---------------------------------------------------------------------------
// Main kernel: persistent blocks + ticket; 64-reg cap, 4 blocks/SM resident.
// grid = 592, block = 256 (warp w owns j = j0 + w within each tile).
// ---------------------------------------------------------------------------
__global__ __launch_bounds__(256, 4)
void attn_main_kernel(const float4* __restrict__ key4,
                      const float4* __restrict__ value4,
                      float* __restrict__ out) {
    const int tid  = threadIdx.x;
    const int w    = tid >> 5;
    const int lane = tid & 31;

    __shared__ int    s_tile;
    __shared__ float4 vbar_sh[G * 64];         // [jj][64 float4]

    for (;;) {
        __syncthreads();                        // vbar_sh reuse + s_tile safety
        if (tid == 0) s_tile = atomicAdd(&g_ticket, 1);
        __syncthreads();
        const int tile = s_tile;
        if (tile >= NTILES) return;

        const int bi = tile >> 3;               // (b*L + i), 0..127
        const int j0 = (tile & 7) * G;
        const int j  = j0 + w;

        const float4* qk4 = reinterpret_cast<const float4*>(g_Qk) + bi * 64;
        const float4 qk0 = qk4[lane];
        const float4 qk1 = qk4[32 + lane];

        const size_t base = (size_t)(bi * DL + j) * (DT * 64);   // float4 units
        const float4* kp = key4 + base;
        const float4* vp = value4 + base;

        // ---- Phase A: eager tree fold, <=4 live score regs ----
        // items in bit-reversed t order; each item covers {t, t+16}
        float h0, h1, myscore;
        {
            float m08 = fold2(score_pair(kp, lane, qk0, qk1, 0),
                              score_pair(kp, lane, qk0, qk1, 8), 8, lane);
            float m4  = fold2(score_pair(kp, lane, qk0, qk1, 4),
                              score_pair(kp, lane, qk0, qk1, 12), 8, lane);
            float q0  = fold2(m08, m4, 4, lane);
            float m2  = fold2(score_pair(kp, lane, qk0, qk1, 2),
                              score_pair(kp, lane, qk0, qk1, 10), 8, lane);
            float m6  = fold2(score_pair(kp, lane, qk0, qk1, 6),
                              score_pair(kp, lane, qk0, qk1, 14), 8, lane);
            float q1  = fold2(m2, m6, 4, lane);
            h0 = fold2(q0, q1, 2, lane);        // all even t
        }
        {
            float m1  = fold2(score_pair(kp, lane, qk0, qk1, 1),
                              score_pair(kp, lane, qk0, qk1, 9), 8, lane);
            float m5  = fold2(score_pair(kp, lane, qk0, qk1, 5),
                              score_pair(kp, lane, qk0, qk1, 13), 8, lane);
            float q2  = fold2(m1, m5, 4, lane);
            float m3  = fold2(score_pair(kp, lane, qk0, qk1, 3),
                              score_pair(kp, lane, qk0, qk1, 11), 8, lane);
            float m7  = fold2(score_pair(kp, lane, qk0, qk1, 7),
                              score_pair(kp, lane, qk0, qk1, 15), 8, lane);
            float q3  = fold2(m3, m7, 4, lane);
            h1 = fold2(q2, q3, 2, lane);        // all odd t
        }
        myscore = fold2(h0, h1, 1, lane);       // lane l holds score[t=l]

        // ---- warp-local softmax over T=32 ----
        float m = myscore;
#pragma unroll
        for (int off = 16; off; off >>= 1)
            m = fmaxf(m, __shfl_xor_sync(0xffffffffu, m, off));
        const float ex = __expf(myscore - m);
        float ssum = ex;
#pragma unroll
        for (int off = 16; off; off >>= 1)
            ssum += __shfl_xor_sync(0xffffffffu, ssum, off);
        const float a = ex / ssum;              // attn[t = lane]

        // ---- Phase B: vbar[d] = sum_t attn[t] * value[t,d] ----
        float4 acc0 = make_float4(0.f, 0.f, 0.f, 0.f);
        float4 acc1 = make_float4(0.f, 0.f, 0.f, 0.f);
#pragma unroll
        for (int t = 0; t < DT; t++) {
            const float at = __shfl_sync(0xffffffffu, a, t);
            const float4 v0 = __ldcs(vp + t * 64 + lane);
            const float4 v1 = __ldcs(vp + t * 64 + 32 + lane);
            acc0.x += at * v0.x; acc0.y += at * v0.y;
            acc0.z += at * v0.z; acc0.w += at * v0.w;
            acc1.x += at * v1.x; acc1.y += at * v1.y;
            acc1.z += at * v1.z; acc1.w += at * v1.w;
        }
        vbar_sh[w * 64 + lane]      = acc0;
        vbar_sh[w * 64 + 32 + lane] = acc1;
        __syncthreads();

        // ---- Phase C: out[j0+jj, f] = bcomb[f] + sum_d vbar[jj][d]*WcombT[d,f] ----
        const int f = tid;
        float acc[G];
        const float bc = g_bcomb[f];
#pragma unroll
        for (int jj = 0; jj < G; jj++) acc[jj] = bc;

#pragma unroll 4
        for (int d4 = 0; d4 < 64; d4++) {
            const float* wt = &g_WcombT[(size_t)(d4 * 4) * DD + f];  // coalesced over f
            const float w0 = wt[0];
            const float w1 = wt[DD];
            const float w2 = wt[2 * DD];
            const float w3 = wt[3 * DD];
#pragma unroll
            for (int jj = 0; jj < G; jj++) {
                const float4 v = vbar_sh[jj * 64 + d4];
                acc[jj] += v.x * w0 + v.y * w1 + v.z * w2 + v.w * w3;
            }
        }

        const size_t obase = (size_t)(bi * DL + j0) * DD + f;
#pragma unroll
        for (int jj = 0; jj < G; jj++)
            out[obase + (size_t)jj * DD] = acc[jj];
    }
}

// ---------------------------------------------------------------------------
// Launch. Input order: key, value, query, Wk, bk, Wv, bv, Wq, bq, Wf, bf
// ---------------------------------------------------------------------------
extern "C" void kernel_launch(void* const* d_in, const int* in_sizes, int n_in,
                              void* d_out, int out_size) {
    const float* key   = (const float*)d_in[0];
    const float* value = (const float*)d_in[1];
    const float* query = (const float*)d_in[2];
    const float* Wk    = (const float*)d_in[3];
    // bk (d_in[4]) cancels under softmax — unused.
    const float* Wv    = (const float*)d_in[5];
    const float* bv    = (const float*)d_in[6];
    const float* Wq    = (const float*)d_in[7];
    const float* bq    = (const float*)d_in[8];
    const float* Wf    = (const float*)d_in[9];
    const float* bf    = (const float*)d_in[10];
    float* out = (float*)d_out;

    prologue_kernel<<<193, dim3(32, 32)>>>(query, Wq, bq, Wk, Wv, bv, Wf, bf);

    attn_main_kernel<<<592, 256>>>(
        reinterpret_cast<const float4*>(key),
        reinterpret_cast<const float4*>(value),
        out);
}